// round 9
// baseline (speedup 1.0000x reference)
#include <cuda_runtime.h>
#include <cuda_bf16.h>

// SimpleLSTM: B=64, T=2048, H=512.
// Persistent kernel: 128 CTAs = 4 batch-groups x 32 hidden-groups.
// W_hh slice in SMEM (row-permuted, conflict-free), c in registers,
// per-step cross-CTA h exchange via L2 + per-group acquire/release flags.
// Warp-local K-sliced h staging (8 x LDG.128 per lane, no staging barrier),
// all-thread spin, fc head fused after a group-local completion spin.

#define B_    64
#define T_    2048
#define H_    512
#define NCTA  128
#define NTHR  256
#define BS_   16
#define HS_   16
#define ROWS  64

#define OFF_W    0            // [512][64]    32768 floats (128 KB), row-permuted
#define OFF_H    32768        // [512][16]     8192 floats (32 KB)
#define OFF_RED  40960        // [8][8][64]f2  8192 floats (32 KB)
#define SMEM_FLOATS 49152
#define SMEM_BYTES  (SMEM_FLOATS * 4)

#define FLAGSTR 32            // 128B stride between counters

__device__ float    g_hall[(size_t)T_ * H_ * B_];
__device__ unsigned g_done[(T_ + 1) * 4 * FLAGSTR];

typedef unsigned long long ull;

__device__ __forceinline__ ull dup2(float x) {
    ull r; unsigned u = __float_as_uint(x);
    asm("mov.b64 %0, {%1, %1};" : "=l"(r) : "r"(u));
    return r;
}
__device__ __forceinline__ void fma2(ull& d, ull a, ull b) {
    asm("fma.rn.f32x2 %0, %1, %2, %0;" : "+l"(d) : "l"(a), "l"(b));
}
__device__ __forceinline__ float sigm(float x) {
    return __fdividef(1.0f, 1.0f + __expf(-x));
}
__device__ __forceinline__ float tanh_f(float x) {
    return __fdividef(2.0f, 1.0f + __expf(-2.0f * x)) - 1.0f;
}
__device__ __forceinline__ unsigned ld_acq(const unsigned* p) {
    unsigned v;
    asm volatile("ld.acquire.gpu.global.u32 %0, [%1];" : "=r"(v) : "l"(p) : "memory");
    return v;
}

__global__ void lstm_init_kernel() {
    int i = blockIdx.x * blockDim.x + threadIdx.x;
    if (i < (T_ + 1) * 4 * FLAGSTR) g_done[i] = 0u;
}

__global__ void __launch_bounds__(NTHR, 1)
lstm_persistent_kernel(const float* __restrict__ x,
                       const float* __restrict__ W_ih,
                       const float* __restrict__ W_hh,
                       const float* __restrict__ b_ih,
                       const float* __restrict__ b_hh,
                       const float* __restrict__ W_fc,
                       const float* __restrict__ b_fc,
                       float* __restrict__ out) {
    extern __shared__ float sm[];
    float* sm_W    = sm + OFF_W;
    float* sm_H    = sm + OFF_H;
    ull*   sm_red  = (ull*)(sm + OFF_RED);
    float* sm_redf = sm + OFF_RED;

    const int tid   = threadIdx.x;
    const int cta   = blockIdx.x;
    const int gh    = cta >> 2;
    const int gb    = cta & 3;
    const int unit0 = gh * HS_;
    const int b0    = gb * BS_;

    const int w    = tid >> 5;            // warp -> K slice [w*64, w*64+64)
    const int lane = tid & 31;
    const int rt   = lane & 15;
    const int bg   = lane >> 4;

    const int j  = tid & 15;              // elementwise (bb, j)
    const int bb = tid >> 4;
    const int bp = bb >> 1;
    const int bc = bb & 1;

    // ---- one-time preload: W slice, slot s = rt*4+r holds local row r*16+rt ----
    for (int idx = tid; idx < ROWS * H_; idx += NTHR) {
        int s = idx >> 9;
        int k = idx & 511;
        int rl = ((s & 3) << 4) + (s >> 2);
        int G = ((rl >> 4) << 9) + unit0 + (rl & 15);
        sm_W[k * 64 + s] = W_hh[(size_t)G * H_ + k];
    }
    // hoist per-thread gate row params into registers
    float wih_r[4], bias_r[4];
#pragma unroll
    for (int g = 0; g < 4; ++g) {
        int G = (g << 9) + unit0 + j;
        wih_r[g]  = __ldg(&W_ih[G]);
        bias_r[g] = __ldg(&b_ih[G]) + __ldg(&b_hh[G]);
    }
    __syncthreads();

    float c_reg = 0.0f;

    const float* Wp = sm_W + (w * 64) * 64 + rt * 4;
    const float* Hp = sm_H + (w * 64) * 16 + bg * 8;
    float* sm_Hw = sm_H + (w * 64) * 16;          // own staging slice (1024 floats)

    const float* xrow = x + (b0 + bb) * T_;

    for (int t = 0; t < T_; ++t) {
        // ---- all threads wait for this batch-group's h_{t-1} ----
        if (t > 0) {
            const unsigned* f = g_done + ((t << 2) + gb) * FLAGSTR;
            while (ld_acq(f) < 32u) { }
        }
        // prefetch x for the cell update (latency hides under GEMM)
        float xv = __ldcg(xrow + t);

        // ---- warp-local staging of own K slice [64][16] = 256 float4 chunks ----
        if (t == 0) {
#pragma unroll
            for (int it = 0; it < 32; ++it) sm_Hw[lane * 32 + it] = 0.0f;
        } else {
            const float* hsrc = g_hall + (size_t)(t - 1) * H_ * B_ + (size_t)(w * 64) * B_;
#pragma unroll
            for (int it = 0; it < 8; ++it) {
                int id = lane + it * 32;          // 0..255 float4 chunks
                int k  = id >> 2;                 // 0..63
                int cc = id & 3;
                float4 v = __ldcg((const float4*)(hsrc + k * B_ + b0 + cc * 4));
                *(float4*)(sm_Hw + k * 16 + cc * 4) = v;
            }
        }
        __syncwarp();

        // ---- GEMM partials: rows {r*16+rt}, 4 batch-pairs/lane, K=64 ----
        ull acc[4][4];
#pragma unroll
        for (int r = 0; r < 4; ++r)
#pragma unroll
            for (int p = 0; p < 4; ++p) acc[r][p] = 0ull;

#pragma unroll 4
        for (int kk = 0; kk < 64; ++kk) {
            float4 wv = *(const float4*)(Wp + kk * 64);
            ulonglong2 hA = *(const ulonglong2*)(Hp + kk * 16);
            ulonglong2 hB = *(const ulonglong2*)(Hp + kk * 16 + 4);
            ull w0 = dup2(wv.x), w1 = dup2(wv.y), w2 = dup2(wv.z), w3 = dup2(wv.w);
            fma2(acc[0][0], w0, hA.x); fma2(acc[0][1], w0, hA.y);
            fma2(acc[0][2], w0, hB.x); fma2(acc[0][3], w0, hB.y);
            fma2(acc[1][0], w1, hA.x); fma2(acc[1][1], w1, hA.y);
            fma2(acc[1][2], w1, hB.x); fma2(acc[1][3], w1, hB.y);
            fma2(acc[2][0], w2, hA.x); fma2(acc[2][1], w2, hA.y);
            fma2(acc[2][2], w2, hB.x); fma2(acc[2][3], w2, hB.y);
            fma2(acc[3][0], w3, hA.x); fma2(acc[3][1], w3, hA.y);
            fma2(acc[3][2], w3, hB.x); fma2(acc[3][3], w3, hB.y);
        }

#pragma unroll
        for (int r = 0; r < 4; ++r)
#pragma unroll
            for (int p = 0; p < 4; ++p) {
                int row = (r << 4) + rt;
                int pp  = (bg << 2) + p;
                sm_red[w * 512 + pp * 64 + row] = acc[r][p];
            }
        __syncthreads();

        // ---- reduce 8 K-slices + cell update ----
        float gate[4];
#pragma unroll
        for (int g = 0; g < 4; ++g) {
            int row = (g << 4) + j;
            const float* rp = sm_redf + bp * 128 + row * 2 + bc;
            float s = 0.0f;
#pragma unroll
            for (int ww = 0; ww < 8; ++ww) s += rp[ww * 1024];
            gate[g] = s + xv * wih_r[g] + bias_r[g];
        }
        float ig = sigm(gate[0]);
        float fg = sigm(gate[1]);
        float gg = tanh_f(gate[2]);
        float og = sigm(gate[3]);
        c_reg = fg * c_reg + ig * gg;
        float h = og * tanh_f(c_reg);

        __stcg(&g_hall[((size_t)t * H_ + unit0 + j) * B_ + b0 + bb], h);
        if (t == T_ - 1) {
            out[B_ * T_ + (b0 + bb) * H_ + unit0 + j]           = h;      // h_n
            out[B_ * T_ + B_ * H_ + (b0 + bb) * H_ + unit0 + j] = c_reg;  // c_n
        }

        __syncthreads();
        if (tid == 0) {
            __threadfence();
            unsigned* f = g_done + (((t + 1) << 2) + gb) * FLAGSTR;
            asm volatile("red.relaxed.gpu.global.add.u32 [%0], %1;"
                         :: "l"(f), "r"(1u) : "memory");
        }
    }

    // ================= fused FC head =================
    // wait until all 32 CTAs of this batch-group finished all T steps
    {
        const unsigned* f = g_done + ((T_ << 2) + gb) * FLAGSTR;
        while (ld_acq(f) < 32u) { }
    }
    // stage W_fc into sm_H (reused)
    for (int i = tid; i < H_; i += NTHR) sm_H[i] = __ldg(&W_fc[i]);
    __syncthreads();

    const float bfc = __ldg(&b_fc[0]);
    // this CTA: t in [gh*64, gh*64+64), batches b0..b0+15 (4 per thread)
    int tt = gh * 64 + (tid >> 2);
    int bq = b0 + (tid & 3) * 4;
    const float* hp = g_hall + (size_t)tt * H_ * B_ + bq;
    float s0 = 0.f, s1 = 0.f, s2 = 0.f, s3 = 0.f;
#pragma unroll 8
    for (int u = 0; u < H_; ++u) {
        float4 v = __ldcg((const float4*)(hp + (size_t)u * B_));
        float wf = sm_H[u];
        s0 = fmaf(v.x, wf, s0);
        s1 = fmaf(v.y, wf, s1);
        s2 = fmaf(v.z, wf, s2);
        s3 = fmaf(v.w, wf, s3);
    }
    out[(bq + 0) * T_ + tt] = s0 + bfc;
    out[(bq + 1) * T_ + tt] = s1 + bfc;
    out[(bq + 2) * T_ + tt] = s2 + bfc;
    out[(bq + 3) * T_ + tt] = s3 + bfc;
}

extern "C" void kernel_launch(void* const* d_in, const int* in_sizes, int n_in,
                              void* d_out, int out_size) {
    (void)in_sizes; (void)n_in; (void)out_size;
    const float* x    = (const float*)d_in[0];
    const float* W_ih = (const float*)d_in[1];
    const float* W_hh = (const float*)d_in[2];
    const float* b_ih = (const float*)d_in[3];
    const float* b_hh = (const float*)d_in[4];
    const float* W_fc = (const float*)d_in[5];
    const float* b_fc = (const float*)d_in[6];
    float* out = (float*)d_out;

    static bool attr_set = false;
    if (!attr_set) {
        cudaFuncSetAttribute(lstm_persistent_kernel,
                             cudaFuncAttributeMaxDynamicSharedMemorySize,
                             SMEM_BYTES);
        attr_set = true;
    }

    lstm_init_kernel<<<((T_ + 1) * 4 * FLAGSTR + 255) / 256, 256>>>();
    lstm_persistent_kernel<<<NCTA, NTHR, SMEM_BYTES>>>(x, W_ih, W_hh, b_ih, b_hh,
                                                       W_fc, b_fc, out);
}